// round 17
// baseline (speedup 1.0000x reference)
#include <cuda_runtime.h>
#include <cuda_bf16.h>
#include <cstdint>

#define N_EMBD        256
#define N_INPUTS      66
#define N_LEVELS      8
#define AND_PER_LEVEL 4096
#define NOT_PER_LEVEL 2048
#define LEVEL_N       (AND_PER_LEVEL + NOT_PER_LEVEL)
#define N_HIDDEN      1024
#define N_HID_LAYERS  8
#define LN_EPS        1e-5f

// ---------------------------------------------------------------------------
// Scratch: static device globals. Weights stored TRANSPOSED [N][K] row-major
// (k-contiguous) so B fragments load with plain non-trans ldmatrix.
// ---------------------------------------------------------------------------
__device__ __align__(256) __nv_bfloat16 g_winT_hi [(size_t)1024 * 512];
__device__ __align__(256) __nv_bfloat16 g_winT_lo [(size_t)1024 * 512];
__device__ __align__(256) __nv_bfloat16 g_whidT_hi[(size_t)8 * 1024 * 1024];
__device__ __align__(256) __nv_bfloat16 g_whidT_lo[(size_t)8 * 1024 * 1024];
__device__ __align__(256) __nv_bfloat16 g_woutT_hi[(size_t)256 * 1024];
__device__ __align__(256) __nv_bfloat16 g_woutT_lo[(size_t)256 * 1024];
__device__ __align__(256) __nv_bfloat16 g_act0_hi [(size_t)4096 * 1024];
__device__ __align__(256) __nv_bfloat16 g_act0_lo [(size_t)4096 * 1024];
__device__ __align__(256) __nv_bfloat16 g_act1_hi [(size_t)4096 * 1024];
__device__ __align__(256) __nv_bfloat16 g_act1_lo [(size_t)4096 * 1024];

// ---------------------------------------------------------------------------
__device__ __forceinline__ void split2(float v, __nv_bfloat16& hi, __nv_bfloat16& lo) {
    hi = __float2bfloat16(v);
    lo = __float2bfloat16(v - __bfloat162float(hi));
}

__device__ __forceinline__ uint32_t smem_u32(const void* p) {
    uint32_t a;
    asm("{ .reg .u64 t; cvta.to.shared.u64 t, %1; cvt.u32.u64 %0, t; }" : "=r"(a) : "l"(p));
    return a;
}

#define CP_ASYNC16(dst, src) \
    asm volatile("cp.async.cg.shared.global [%0], [%1], 16;" :: "r"(dst), "l"(src) : "memory")
#define CP_COMMIT() asm volatile("cp.async.commit_group;" ::: "memory")
#define CP_WAIT1()  asm volatile("cp.async.wait_group 1;" ::: "memory")
#define CP_WAIT0()  asm volatile("cp.async.wait_group 0;" ::: "memory")

__device__ __forceinline__ void ldsm4(uint32_t r[4], uint32_t addr) {
    asm volatile("ldmatrix.sync.aligned.m8n8.x4.shared.b16 {%0,%1,%2,%3}, [%4];"
                 : "=r"(r[0]), "=r"(r[1]), "=r"(r[2]), "=r"(r[3]) : "r"(addr));
}

__device__ __forceinline__ void mma_bf16(float c[4], const uint32_t a[4], const uint32_t b[2]) {
    asm volatile("mma.sync.aligned.m16n8k16.row.col.f32.bf16.bf16.f32 "
                 "{%0,%1,%2,%3}, {%4,%5,%6,%7}, {%8,%9}, {%0,%1,%2,%3};"
                 : "+f"(c[0]), "+f"(c[1]), "+f"(c[2]), "+f"(c[3])
                 : "r"(a[0]), "r"(a[1]), "r"(a[2]), "r"(a[3]), "r"(b[0]), "r"(b[1]));
}

// ---------------------------------------------------------------------------
// Elementwise kernels
// ---------------------------------------------------------------------------
// Transpose + split: src [R,C] f32 (layer z) -> dst [C][R] bf16 hi/lo.
// dst_sel: 0 -> W_in, 1 -> W_hid, 2 -> W_out
__global__ void tsplit_kernel(const float* __restrict__ src, int R, int C, int dst_sel) {
    __shared__ float t[32][33];
    const int layer = blockIdx.z;
    const float* sp = src + (size_t)layer * R * C;
    __nv_bfloat16 *hi, *lo;
    if (dst_sel == 0)      { hi = g_winT_hi;  lo = g_winT_lo; }
    else if (dst_sel == 1) { hi = g_whidT_hi + (size_t)layer * R * C;
                             lo = g_whidT_lo + (size_t)layer * R * C; }
    else                   { hi = g_woutT_hi; lo = g_woutT_lo; }
    const int c0 = blockIdx.x * 32, r0 = blockIdx.y * 32;
    const int tx = threadIdx.x, ty = threadIdx.y;
#pragma unroll
    for (int j = ty; j < 32; j += 8) t[j][tx] = sp[(size_t)(r0 + j) * C + c0 + tx];
    __syncthreads();
#pragma unroll
    for (int j = ty; j < 32; j += 8) {
        float v = t[tx][j];   // src[(r0+tx)*C + (c0+j)]
        __nv_bfloat16 h, l; split2(v, h, l);
        size_t o = (size_t)(c0 + j) * R + r0 + tx;   // dst[n][k]
        hi[o] = h; lo[o] = l;
    }
}

__global__ void init_kernel(const float* __restrict__ embd, float* __restrict__ out) {
    int i = blockIdx.x * blockDim.x + threadIdx.x;
    if (i < N_INPUTS * N_EMBD) out[i] = embd[i];
}

// Fused gather (h = [embd[xa], embd[ya]] -> act0, 4096x512 hi/lo) + NOT scatter.
#define GATHER_WORK (AND_PER_LEVEL * 512)
#define NOT_WORK    (NOT_PER_LEVEL * N_EMBD)
__global__ void gather_not_kernel(float* __restrict__ node,
                                  const int* __restrict__ xe, const int* __restrict__ ye,
                                  int s) {
    int i = blockIdx.x * blockDim.x + threadIdx.x;
    if (i < GATHER_WORK) {
        int m = i >> 9, c = i & 511;
        int src = (c < 256) ? xe[s + m] : ye[s + m];
        float v = node[(size_t)src * N_EMBD + (c & 255)];
        __nv_bfloat16 h, l; split2(v, h, l);
        g_act0_hi[i] = h; g_act0_lo[i] = l;
    } else if (i < GATHER_WORK + NOT_WORK) {
        int j = i - GATHER_WORK;
        int r = j >> 8, c = j & 255;
        int src = xe[s + AND_PER_LEVEL + r];
        node[(size_t)(s + AND_PER_LEVEL + r) * N_EMBD + c] = -node[(size_t)src * N_EMBD + c];
    }
}

// ---------------------------------------------------------------------------
// Split-bf16 GEMM via raw mma.sync.m16n8k16 + ldmatrix. 128 threads / 4 warps.
// C = (Ahi+Alo)@(Bhi+Blo) dropping lo*lo. Block tile BM x BN, K-chunk 32/stage.
// Warp grid: WROWS x WCOLS (WCOLS = BN/64); warp tile WM x 64, MF = WM/16.
// Hidden: 128x64 -> warp tile 32x64, acc=64 regs, OCC=3 (12 warps/SM).
// Output: 64x256 -> warp tile 64x64, acc=128 regs, OCC=2.
// Per k16: hh -> lh -> hl (acc reuse distance = MF*8 >= 16).
// 2-stage cp.async pipeline.
// fuse=1: relu(x+bias) -> bf16 hi/lo act[out_sel]. fuse=2: bias+LayerNorm -> outp.
// ---------------------------------------------------------------------------
#define LD40 40   // halves per smem row (80 B pitch: 16B-aligned, ldmatrix conflict-free)

template<int BM, int BN, int OCC>
__global__ __launch_bounds__(128, OCC) void gemm_mma(
    int K, int Nout, int a_sel, int b_sel, int layer, int out_sel, int fuse,
    const float* __restrict__ bias, float* __restrict__ outp, int s,
    const float* __restrict__ ln_g, const float* __restrict__ ln_b) {

    constexpr int WCOLS = BN / 64;          // 1 (hidden) or 4 (output)
    constexpr int WROWS = 4 / WCOLS;        // 4 or 1
    constexpr int WM    = BM / WROWS;       // 32 or 64
    constexpr int MF    = WM / 16;          // 2 or 4
    constexpr uint32_t ATILE = (uint32_t)BM * LD40 * 2u;   // bytes per A half-tile
    constexpr uint32_t BTILE = (uint32_t)BN * LD40 * 2u;
    constexpr uint32_t SS    = 2u * ATILE + 2u * BTILE;    // stage bytes

    extern __shared__ __align__(128) char dsm[];

    const int tid = threadIdx.x, warpId = tid >> 5, lane = tid & 31;
    const int wm = warpId / WCOLS, wn = warpId % WCOLS;
    const int rowBase = blockIdx.y * BM;
    const int colBase = blockIdx.x * BN;

    const __nv_bfloat16* Ahi = a_sel ? g_act1_hi : g_act0_hi;
    const __nv_bfloat16* Alo = a_sel ? g_act1_lo : g_act0_lo;
    const __nv_bfloat16 *Bhi, *Blo;
    if (b_sel == 0)      { Bhi = g_winT_hi;  Blo = g_winT_lo; }
    else if (b_sel == 1) { Bhi = g_whidT_hi + (size_t)layer * N_HIDDEN * N_HIDDEN;
                           Blo = g_whidT_lo + (size_t)layer * N_HIDDEN * N_HIDDEN; }
    else                 { Bhi = g_woutT_hi; Blo = g_woutT_lo; }

    const uint32_t sm0 = smem_u32(dsm);

    // ldmatrix per-lane selectors (PTX ISA fragment layouts)
    const uint32_t aRow = lane & 15;
    const uint32_t aCol = (lane >> 4) << 3;
    const uint32_t bRow = ((lane >> 4) << 3) + (lane & 7);
    const uint32_t bCol = ((lane >> 3) & 1) << 3;

    float acc[MF][8][4];
#pragma unroll
    for (int m = 0; m < MF; m++)
#pragma unroll
        for (int t = 0; t < 8; t++)
#pragma unroll
            for (int j = 0; j < 4; j++) acc[m][t][j] = 0.0f;

    const int NK = K >> 5;   // 32-K stages

    auto load_stage = [&](int stg, int k0) {
        const uint32_t sb = sm0 + (uint32_t)stg * SS;
#pragma unroll
        for (int h = 0; h < 2; h++) {
            const __nv_bfloat16* ap = h ? Alo : Ahi;
            const uint32_t so = sb + h * ATILE;
#pragma unroll
            for (int i = 0; i < (BM * 4) / 128; i++) {
                int v = tid + i * 128;
                int r = v >> 2, cv = v & 3;
                CP_ASYNC16(so + (uint32_t)(r * LD40 + cv * 8) * 2u,
                           ap + (size_t)(rowBase + r) * K + k0 + cv * 8);
            }
        }
#pragma unroll
        for (int h = 0; h < 2; h++) {
            const __nv_bfloat16* bp = h ? Blo : Bhi;
            const uint32_t so = sb + 2u * ATILE + h * BTILE;
#pragma unroll
            for (int i = 0; i < (BN * 4) / 128; i++) {
                int v = tid + i * 128;
                int r = v >> 2, cv = v & 3;
                CP_ASYNC16(so + (uint32_t)(r * LD40 + cv * 8) * 2u,
                           bp + (size_t)(colBase + r) * K + k0 + cv * 8);
            }
        }
        CP_COMMIT();
    };

    load_stage(0, 0);
    load_stage(1, 32);

    for (int kt = 0; kt < NK; kt++) {
        if (kt + 1 < NK) CP_WAIT1(); else CP_WAIT0();
        __syncthreads();

        const uint32_t sb  = sm0 + (uint32_t)(kt & 1) * SS;
        const uint32_t aHi = sb, aLo = sb + ATILE;
        const uint32_t bHi = sb + 2u * ATILE, bLo = bHi + BTILE;

#pragma unroll
        for (int ks = 0; ks < 32; ks += 16) {
            const uint32_t aoff = ((wm * WM + aRow) * LD40 + ks + aCol) * 2u;
            uint32_t ah[MF][4];
#pragma unroll
            for (int m = 0; m < MF; m++)
                ldsm4(ah[m], aHi + aoff + (uint32_t)(m * 16 * LD40 * 2));
            uint32_t bh[4][4];
#pragma unroll
            for (int p = 0; p < 4; p++)
                ldsm4(bh[p], bHi + ((wn * 64 + p * 16 + bRow) * LD40 + ks + bCol) * 2u);
            // hi*hi
#pragma unroll
            for (int m = 0; m < MF; m++)
#pragma unroll
                for (int t = 0; t < 8; t++)
                    mma_bf16(acc[m][t], ah[m], &bh[t >> 1][(t & 1) * 2]);
            // lo*hi
            {
                uint32_t al[MF][4];
#pragma unroll
                for (int m = 0; m < MF; m++)
                    ldsm4(al[m], aLo + aoff + (uint32_t)(m * 16 * LD40 * 2));
#pragma unroll
                for (int m = 0; m < MF; m++)
#pragma unroll
                    for (int t = 0; t < 8; t++)
                        mma_bf16(acc[m][t], al[m], &bh[t >> 1][(t & 1) * 2]);
            }
            // hi*lo
            {
                uint32_t bl[4][4];
#pragma unroll
                for (int p = 0; p < 4; p++)
                    ldsm4(bl[p], bLo + ((wn * 64 + p * 16 + bRow) * LD40 + ks + bCol) * 2u);
#pragma unroll
                for (int m = 0; m < MF; m++)
#pragma unroll
                    for (int t = 0; t < 8; t++)
                        mma_bf16(acc[m][t], ah[m], &bl[t >> 1][(t & 1) * 2]);
            }
        }

        if (kt + 2 < NK) {
            __syncthreads();
            load_stage(kt & 1, (kt + 2) * 32);
        }
    }
    __syncthreads();

    // acc layout: c0,c1 = row (lane>>2), cols (lane&3)*2,+1; c2,c3 = row+8.
    const int rl = lane >> 2, cl = (lane & 3) * 2;

    if (fuse == 1) {
        __nv_bfloat16* Ohi = out_sel ? g_act1_hi : g_act0_hi;
        __nv_bfloat16* Olo = out_sel ? g_act1_lo : g_act0_lo;
#pragma unroll
        for (int m = 0; m < MF; m++)
#pragma unroll
            for (int t = 0; t < 8; t++) {
                const float* c = acc[m][t];
                const int R = rowBase + wm * WM + m * 16 + rl;
                const int C = colBase + wn * 64 + t * 8 + cl;
                float b0 = __ldg(bias + C), b1 = __ldg(bias + C + 1);
                float v0 = fmaxf(c[0] + b0, 0.0f), v1 = fmaxf(c[1] + b1, 0.0f);
                float v2 = fmaxf(c[2] + b0, 0.0f), v3 = fmaxf(c[3] + b1, 0.0f);
                __nv_bfloat16 h0, l0, h1, l1, h2, l2, h3, l3;
                split2(v0, h0, l0); split2(v1, h1, l1);
                split2(v2, h2, l2); split2(v3, h3, l3);
                size_t g0 = (size_t)R * Nout + C;
                size_t g1 = (size_t)(R + 8) * Nout + C;
                *(__nv_bfloat162*)(Ohi + g0) = __nv_bfloat162(h0, h1);
                *(__nv_bfloat162*)(Olo + g0) = __nv_bfloat162(l0, l1);
                *(__nv_bfloat162*)(Ohi + g1) = __nv_bfloat162(h2, h3);
                *(__nv_bfloat162*)(Olo + g1) = __nv_bfloat162(l2, l3);
            }
    } else {
        // fuse == 2: bias + LayerNorm. BM=64 (wm==0), BN=256, colBase==0.
        float2* s_red = (float2*)dsm;   // [64][WCOLS]
        float2 part[MF][2];
#pragma unroll
        for (int m = 0; m < MF; m++) { part[m][0] = make_float2(0.f, 0.f);
                                       part[m][1] = make_float2(0.f, 0.f); }
#pragma unroll
        for (int m = 0; m < MF; m++)
#pragma unroll
            for (int t = 0; t < 8; t++) {
                float* c = acc[m][t];
                const int C = wn * 64 + t * 8 + cl;
                float b0 = __ldg(bias + C), b1 = __ldg(bias + C + 1);
                c[0] += b0; c[1] += b1; c[2] += b0; c[3] += b1;
                part[m][0].x += c[0] + c[1];
                part[m][0].y += c[0] * c[0] + c[1] * c[1];
                part[m][1].x += c[2] + c[3];
                part[m][1].y += c[2] * c[2] + c[3] * c[3];
            }
#pragma unroll
        for (int m = 0; m < MF; m++)
#pragma unroll
            for (int h = 0; h < 2; h++) {
#pragma unroll
                for (int o = 1; o <= 2; o <<= 1) {
                    part[m][h].x += __shfl_xor_sync(0xFFFFFFFFu, part[m][h].x, o);
                    part[m][h].y += __shfl_xor_sync(0xFFFFFFFFu, part[m][h].y, o);
                }
                if ((lane & 3) == 0)
                    s_red[(m * 16 + h * 8 + rl) * WCOLS + wn] = part[m][h];
            }
        __syncthreads();
#pragma unroll
        for (int m = 0; m < MF; m++)
#pragma unroll
            for (int h = 0; h < 2; h++) {
                const int r = m * 16 + h * 8 + rl;
                float sum = 0.f, sq = 0.f;
#pragma unroll
                for (int w = 0; w < WCOLS; w++) {
                    float2 p = s_red[r * WCOLS + w];
                    sum += p.x; sq += p.y;
                }
                float mu  = sum * (1.0f / N_EMBD);
                float var = sq * (1.0f / N_EMBD) - mu * mu;
                float inv = rsqrtf(var + LN_EPS);
                float* orow = outp + (size_t)(s + rowBase + r) * N_EMBD;
#pragma unroll
                for (int t = 0; t < 8; t++) {
                    const int C = wn * 64 + t * 8 + cl;
                    float g0 = __ldg(ln_g + C), g1 = __ldg(ln_g + C + 1);
                    float bb0 = __ldg(ln_b + C), bb1 = __ldg(ln_b + C + 1);
                    float v0 = (acc[m][t][h * 2 + 0] - mu) * inv * g0 + bb0;
                    float v1 = (acc[m][t][h * 2 + 1] - mu) * inv * g1 + bb1;
                    *(float2*)(orow + C) = make_float2(v0, v1);
                }
            }
    }
}

// ---------------------------------------------------------------------------
// Launch: kernel launches only; graph-capturable; no allocation; no sync.
// First GEMM at launch index 3 (ncu capture slot).
// ---------------------------------------------------------------------------
extern "C" void kernel_launch(void* const* d_in, const int* in_sizes, int n_in,
                              void* d_out, int out_size) {
    (void)in_sizes; (void)n_in; (void)out_size;

    const int*   xe         = (const int*)d_in[1];
    const int*   ye         = (const int*)d_in[2];
    const float* input_embd = (const float*)d_in[3];
    const float* W_in       = (const float*)d_in[4];
    const float* b_in       = (const float*)d_in[5];
    const float* W_hid      = (const float*)d_in[6];
    const float* b_hid      = (const float*)d_in[7];
    const float* W_out      = (const float*)d_in[8];
    const float* b_out      = (const float*)d_in[9];
    const float* ln_g       = (const float*)d_in[10];
    const float* ln_b       = (const float*)d_in[11];
    float*       out        = (float*)d_out;

    // Stage sizes (bytes)
    const uint32_t SS_H = 2u * (128 * LD40 * 2) + 2u * (64 * LD40 * 2);   // 30720 (128x64)
    const uint32_t SS_O = 2u * (64 * LD40 * 2) + 2u * (256 * LD40 * 2);   // 51200 (64x256)
    cudaFuncSetAttribute((const void*)gemm_mma<128, 64, 3>,
                         cudaFuncAttributeMaxDynamicSharedMemorySize, 2 * SS_H);
    cudaFuncSetAttribute((const void*)gemm_mma<64, 256, 2>,
                         cudaFuncAttributeMaxDynamicSharedMemorySize, 2 * SS_O);

    const dim3 gridH(N_HIDDEN / 64, AND_PER_LEVEL / 128);   // (16, 32) = 512 CTAs
    const dim3 gridO(1, AND_PER_LEVEL / 64);                // (1, 64) = 64 CTAs
    const int  gnBlocks = (GATHER_WORK + NOT_WORK + 255) / 256;
    const dim3 tb(32, 8);

    // --- prologue arranged so launch #3 is a GEMM (ncu capture target) ---
    tsplit_kernel<<<dim3(1024 / 32, 512 / 32, 1), tb>>>(W_in, 512, 1024, 0);      // 0
    init_kernel<<<(N_INPUTS * N_EMBD + 255) / 256, 256>>>(input_embd, out);       // 1
    gather_not_kernel<<<gnBlocks, 256>>>(out, xe, ye, N_INPUTS);                  // 2
    gemm_mma<128, 64, 3><<<gridH, 128, 2 * SS_H>>>(512, N_HIDDEN, 0, 0, 0, 1, 1,
                                                   b_in, nullptr, 0, nullptr, nullptr); // 3
    tsplit_kernel<<<dim3(1024 / 32, 1024 / 32, 8), tb>>>(W_hid, 1024, 1024, 1);   // 4
    tsplit_kernel<<<dim3(256 / 32, 1024 / 32, 1), tb>>>(W_out, 1024, 256, 2);     // 5

    for (int l = 0; l < N_LEVELS; l++) {
        const int s = N_INPUTS + l * LEVEL_N;

        if (l > 0) {
            gather_not_kernel<<<gnBlocks, 256>>>(out, xe, ye, s);
            gemm_mma<128, 64, 3><<<gridH, 128, 2 * SS_H>>>(512, N_HIDDEN, 0, 0, 0, 1, 1,
                                                           b_in, nullptr, 0, nullptr, nullptr);
        }

        for (int i = 0; i < N_HID_LAYERS; i++) {
            int a_sel = (i & 1) ? 0 : 1;
            int o_sel = 1 - a_sel;
            gemm_mma<128, 64, 3><<<gridH, 128, 2 * SS_H>>>(N_HIDDEN, N_HIDDEN, a_sel, 1, i, o_sel, 1,
                                                           b_hid + (size_t)i * N_HIDDEN,
                                                           nullptr, 0, nullptr, nullptr);
        }

        gemm_mma<64, 256, 2><<<gridO, 128, 2 * SS_O>>>(N_HIDDEN, N_EMBD, 1, 2, 0, 0, 2,
                                                       b_out, out, s, ln_g, ln_b);
    }
}